// round 7
// baseline (speedup 1.0000x reference)
#include <cuda_runtime.h>
#include <cuda_bf16.h>
#include <cstdint>

// Problem constants
#define S_LEN  2048
#define BATCH  2
#define EMBED  1024
#define NHEAD  16
#define RANK   32
#define HDIM   64
#define MROWS  (BATCH * S_LEN)   // 4096
#define QKCOLS (NHEAD * RANK)    // 512
#define BH     (BATCH * NHEAD)   // 32

// ---------------------------------------------------------------------------
// Scratch (__device__ globals)
// ---------------------------------------------------------------------------
__device__ __nv_bfloat16 g_Xhi [MROWS * EMBED];
__device__ __nv_bfloat16 g_Xlo [MROWS * EMBED];
__device__ __nv_bfloat16 g_AOhi[MROWS * EMBED];
__device__ __nv_bfloat16 g_AOlo[MROWS * EMBED];

__device__ __nv_bfloat16 g_Wq_hi[QKCOLS * EMBED];
__device__ __nv_bfloat16 g_Wq_lo[QKCOLS * EMBED];
__device__ __nv_bfloat16 g_Wk_hi[QKCOLS * EMBED];
__device__ __nv_bfloat16 g_Wk_lo[QKCOLS * EMBED];
__device__ __nv_bfloat16 g_Wv_hi[EMBED * EMBED];
__device__ __nv_bfloat16 g_Wv_lo[EMBED * EMBED];
__device__ __nv_bfloat16 g_Wo_hi[EMBED * EMBED];
__device__ __nv_bfloat16 g_Wo_lo[EMBED * EMBED];

// Attention-layout tensors
__device__ __nv_bfloat16 g_Qhi [MROWS * QKCOLS];   // [bh][S][32]
__device__ __nv_bfloat16 g_Qlo [MROWS * QKCOLS];
__device__ __nv_bfloat16 g_Khi [MROWS * QKCOLS];
__device__ __nv_bfloat16 g_Klo [MROWS * QKCOLS];
__device__ __nv_bfloat16 g_Vthi[BH * HDIM * S_LEN]; // [bh][d][S]
__device__ __nv_bfloat16 g_Vtlo[BH * HDIM * S_LEN];

// ---------------------------------------------------------------------------
// Helpers (compute_103-safe: mma.sync / ldmatrix / cp.async only)
// ---------------------------------------------------------------------------
__device__ __forceinline__ uint32_t smem_u32(const void* p) {
    uint32_t a;
    asm("{ .reg .u64 t; cvta.to.shared.u64 t, %1; cvt.u32.u64 %0, t; }"
        : "=r"(a) : "l"(p));
    return a;
}

__device__ __forceinline__ void cp16(uint32_t dst, const void* src) {
    asm volatile("cp.async.cg.shared.global [%0], [%1], 16;"
                 :: "r"(dst), "l"(src) : "memory");
}
__device__ __forceinline__ void cp_commit() {
    asm volatile("cp.async.commit_group;" ::: "memory");
}
template<int N> __device__ __forceinline__ void cp_wait() {
    asm volatile("cp.async.wait_group %0;" :: "n"(N) : "memory");
}

__device__ __forceinline__ void ldm_x4(uint32_t& r0, uint32_t& r1,
                                       uint32_t& r2, uint32_t& r3, uint32_t a) {
    asm volatile("ldmatrix.sync.aligned.m8n8.x4.shared.b16 {%0,%1,%2,%3}, [%4];"
                 : "=r"(r0), "=r"(r1), "=r"(r2), "=r"(r3) : "r"(a));
}

__device__ __forceinline__ void mma_bf16(float c[4], const uint32_t a[4],
                                         uint32_t b0, uint32_t b1) {
    asm volatile(
        "mma.sync.aligned.m16n8k16.row.col.f32.bf16.bf16.f32 "
        "{%0,%1,%2,%3}, {%4,%5,%6,%7}, {%8,%9}, {%0,%1,%2,%3};"
        : "+f"(c[0]), "+f"(c[1]), "+f"(c[2]), "+f"(c[3])
        : "r"(a[0]), "r"(a[1]), "r"(a[2]), "r"(a[3]), "r"(b0), "r"(b1));
}

__device__ __forceinline__ uint32_t pack_bf2(float lo, float hi) {
    __nv_bfloat162 t = __float22bfloat162_rn(make_float2(lo, hi));
    return *(uint32_t*)&t;
}

__device__ __forceinline__ void split1(float x, __nv_bfloat16& h, __nv_bfloat16& l) {
    h = __float2bfloat16(x);
    l = __float2bfloat16(x - __bfloat162float(h));
}

// pack (a,b) into bf16x2 hi + bf16x2 residual-lo; a -> lower halfword
__device__ __forceinline__ void split_pack2(float a, float b,
                                            uint32_t& h, uint32_t& l) {
    __nv_bfloat16 ah = __float2bfloat16(a);
    __nv_bfloat16 bh = __float2bfloat16(b);
    float ar = a - __bfloat162float(ah);
    float br = b - __bfloat162float(bh);
    __nv_bfloat162 th(ah, bh);
    h = *(uint32_t*)&th;
    l = pack_bf2(ar, br);
}

// ---------------------------------------------------------------------------
// Conversion kernels
// ---------------------------------------------------------------------------
__global__ __launch_bounds__(256) void split_f32_kernel(
    const float* __restrict__ x, __nv_bfloat16* __restrict__ hi,
    __nv_bfloat16* __restrict__ lo, int n4)
{
    int i = blockIdx.x * 256 + threadIdx.x;
    if (i >= n4) return;
    float4 v = ((const float4*)x)[i];
    __nv_bfloat16 h0, h1, h2, h3, l0, l1, l2, l3;
    split1(v.x, h0, l0); split1(v.y, h1, l1);
    split1(v.z, h2, l2); split1(v.w, h3, l3);
    ((__nv_bfloat162*)hi)[i * 2]     = __nv_bfloat162(h0, h1);
    ((__nv_bfloat162*)hi)[i * 2 + 1] = __nv_bfloat162(h2, h3);
    ((__nv_bfloat162*)lo)[i * 2]     = __nv_bfloat162(l0, l1);
    ((__nv_bfloat162*)lo)[i * 2 + 1] = __nv_bfloat162(l2, l3);
}

// W [1024(K), N] fp32 -> [N][1024] bf16 hi/lo (transposed)
__global__ __launch_bounds__(256) void transpose_split_kernel(
    const float* __restrict__ W, __nv_bfloat16* __restrict__ hi,
    __nv_bfloat16* __restrict__ lo, int N)
{
    __shared__ float t[32][33];
    const int k0 = blockIdx.y * 32;
    const int n0 = blockIdx.x * 32;
    const int tx = threadIdx.x & 31;
    const int ty = threadIdx.x >> 5;
#pragma unroll
    for (int i = 0; i < 4; i++)
        t[ty + i * 8][tx] = W[(size_t)(k0 + ty + i * 8) * N + n0 + tx];
    __syncthreads();
#pragma unroll
    for (int i = 0; i < 4; i++) {
        int n = n0 + ty + i * 8;
        float v = t[tx][ty + i * 8];
        __nv_bfloat16 h, l;
        split1(v, h, l);
        hi[(size_t)n * 1024 + k0 + tx] = h;
        lo[(size_t)n * 1024 + k0 + tx] = l;
    }
}

// ---------------------------------------------------------------------------
// HMMA split-bf16 GEMM with fused epilogues:
//   acc = (Ahi+Alo)[M,1024] @ (Bhi+Blo)[N,1024]^T + bias
// mode 0: fp32 C[M,N]
// mode 1: split bf16 -> QK attention layout [bh][2048][32]
// mode 2: split bf16 -> transposed Vt layout [bh][64][2048] (via smem staging)
// Tiles 128x128x32, cp.async double-buffered, 8 warps (warp tile 32x64).
// ---------------------------------------------------------------------------
#define GEMM_STAGE_BYTES 40960
#define GEMM_SMEM_BYTES  (2 * GEMM_STAGE_BYTES)   // 81920; mode2 staging 66048 fits

__global__ __launch_bounds__(256) void hmma_gemm_kernel(
    const __nv_bfloat16* __restrict__ Ahi, const __nv_bfloat16* __restrict__ Alo,
    const __nv_bfloat16* __restrict__ Bhi, const __nv_bfloat16* __restrict__ Blo,
    const float* __restrict__ bias, int mode,
    float* __restrict__ C, __nv_bfloat16* __restrict__ Ohi,
    __nv_bfloat16* __restrict__ Olo, int N)
{
    extern __shared__ char sm[];
    const uint32_t sb = smem_u32(sm);

    const int tid = threadIdx.x;
    const int wid = tid >> 5;
    const int lane = tid & 31;
    const int warp_m = wid & 3;
    const int warp_n = wid >> 2;
    const int bm = blockIdx.y * 128;
    const int bn = blockIdx.x * 128;

    const int srow = tid >> 2;
    const int sseg = tid & 3;

    auto issue = [&](int c, int stg) {
        const uint32_t base = sb + stg * GEMM_STAGE_BYTES;
        const size_t kb = (size_t)c * 64;
#pragma unroll
        for (int it = 0; it < 2; it++) {
            int row = srow + it * 64;
            uint32_t so = row * 80 + sseg * 16;
            size_t ga = (size_t)(bm + row) * 2048 + kb + sseg * 16;
            size_t gb = (size_t)(bn + row) * 2048 + kb + sseg * 16;
            cp16(base +     0 + so, (const char*)Ahi + ga);
            cp16(base + 10240 + so, (const char*)Alo + ga);
            cp16(base + 20480 + so, (const char*)Bhi + gb);
            cp16(base + 30720 + so, (const char*)Blo + gb);
        }
    };

    float acc[2][8][4];
#pragma unroll
    for (int mf = 0; mf < 2; mf++)
#pragma unroll
        for (int nf = 0; nf < 8; nf++)
#pragma unroll
            for (int k = 0; k < 4; k++) acc[mf][nf][k] = 0.0f;

    issue(0, 0); cp_commit();
    issue(1, 1); cp_commit();

    for (int c = 0; c < 32; c++) {
        cp_wait<1>();
        __syncthreads();
        const uint32_t base = sb + (c & 1) * GEMM_STAGE_BYTES;

#pragma unroll
        for (int ks = 0; ks < 2; ks++) {
            uint32_t lm_off = (lane & 15) * 80 + ks * 32 + (lane >> 4) * 16;
            uint32_t ah[2][4], al[2][4];
#pragma unroll
            for (int mf = 0; mf < 2; mf++) {
                uint32_t aa = base + (warp_m * 32 + mf * 16) * 80 + lm_off;
                ldm_x4(ah[mf][0], ah[mf][1], ah[mf][2], ah[mf][3], aa);
                ldm_x4(al[mf][0], al[mf][1], al[mf][2], al[mf][3], aa + 10240);
            }
#pragma unroll
            for (int p = 0; p < 4; p++) {
                uint32_t ba = base + 20480 + (warp_n * 64 + p * 16) * 80 + lm_off;
                uint32_t h0, h1, h2, h3, o0, o1, o2, o3;
                ldm_x4(h0, h1, h2, h3, ba);
                ldm_x4(o0, o1, o2, o3, ba + 10240);
#pragma unroll
                for (int mf = 0; mf < 2; mf++) {
                    mma_bf16(acc[mf][2 * p],     ah[mf], h0, h2);
                    mma_bf16(acc[mf][2 * p],     ah[mf], o0, o2);
                    mma_bf16(acc[mf][2 * p],     al[mf], h0, h2);
                    mma_bf16(acc[mf][2 * p + 1], ah[mf], h1, h3);
                    mma_bf16(acc[mf][2 * p + 1], ah[mf], o1, o3);
                    mma_bf16(acc[mf][2 * p + 1], al[mf], h1, h3);
                }
            }
        }
        __syncthreads();
        if (c + 2 < 32) issue(c + 2, c & 1);
        cp_commit();   // always commit (empty group keeps wait accounting exact)
    }

    if (mode == 0) {
#pragma unroll
        for (int mf = 0; mf < 2; mf++) {
            int row0 = bm + warp_m * 32 + mf * 16 + (lane >> 2);
#pragma unroll
            for (int nf = 0; nf < 8; nf++) {
                int col = bn + warp_n * 64 + nf * 8 + 2 * (lane & 3);
                float b0 = bias[col], b1 = bias[col + 1];
                float2 v0 = make_float2(acc[mf][nf][0] + b0, acc[mf][nf][1] + b1);
                float2 v1 = make_float2(acc[mf][nf][2] + b0, acc[mf][nf][3] + b1);
                *(float2*)(C + (size_t)row0 * N + col)       = v0;
                *(float2*)(C + (size_t)(row0 + 8) * N + col) = v1;
            }
        }
    } else if (mode == 1) {
        // split -> [bh][2048][32]
#pragma unroll
        for (int mf = 0; mf < 2; mf++) {
            int rowg = bm + warp_m * 32 + mf * 16 + (lane >> 2);
#pragma unroll
            for (int nf = 0; nf < 8; nf++) {
                int col = bn + warp_n * 64 + nf * 8 + 2 * (lane & 3);
                float b0 = bias[col], b1 = bias[col + 1];
                int h = col >> 5, r = col & 31;
#pragma unroll
                for (int half = 0; half < 2; half++) {
                    int rg = rowg + half * 8;
                    int bb = rg >> 11, ii = rg & 2047;
                    size_t dst = (((size_t)(bb * NHEAD + h) * S_LEN) + ii) * RANK + r;
                    uint32_t hv, lv;
                    split_pack2(acc[mf][nf][2 * half] + b0,
                                acc[mf][nf][2 * half + 1] + b1, hv, lv);
                    *(uint32_t*)(Ohi + dst) = hv;
                    *(uint32_t*)(Olo + dst) = lv;
                }
            }
        }
    } else {
        // mode 2: stage fp32 tile in smem, write transposed split Vt
        cp_wait<0>();
        __syncthreads();
        float* st = (float*)sm;   // [128][129]
#pragma unroll
        for (int mf = 0; mf < 2; mf++) {
            int rl = warp_m * 32 + mf * 16 + (lane >> 2);
#pragma unroll
            for (int nf = 0; nf < 8; nf++) {
                int cl = warp_n * 64 + nf * 8 + 2 * (lane & 3);
                float b0 = bias[bn + cl], b1 = bias[bn + cl + 1];
                st[rl * 129 + cl]           = acc[mf][nf][0] + b0;
                st[rl * 129 + cl + 1]       = acc[mf][nf][1] + b1;
                st[(rl + 8) * 129 + cl]     = acc[mf][nf][2] + b0;
                st[(rl + 8) * 129 + cl + 1] = acc[mf][nf][3] + b1;
            }
        }
        __syncthreads();
        int c = tid >> 1, half = tid & 1;
        int colg = bn + c;
        int hh = colg >> 6, dd = colg & 63;
        int bb = bm >> 11;
        int i0 = (bm & 2047) + half * 64;
        size_t ob = (((size_t)(bb * NHEAD + hh)) * HDIM + dd) * S_LEN + i0;
#pragma unroll
        for (int t = 0; t < 64; t += 2) {
            float v0 = st[(half * 64 + t) * 129 + c];
            float v1 = st[(half * 64 + t + 1) * 129 + c];
            uint32_t hv, lv;
            split_pack2(v0, v1, hv, lv);
            *(uint32_t*)(Ohi + ob + t) = hv;
            *(uint32_t*)(Olo + ob + t) = lv;
        }
    }
}

// ---------------------------------------------------------------------------
// HMMA flash attention (split-precision, 4-stage cp.async pipeline).
// Grid (S/128, BH), 256 threads (8 warps, 16 q-rows each).
// Epilogue writes AO hi/lo split directly.
// SMEM: Q hi/lo 20480; 4 stages x (Khi 5120 | Klo 5120 | Vhi 8192 | Vlo 8192)
// ---------------------------------------------------------------------------
#define ATT_Q_BYTES     20480
#define ATT_STAGE_BYTES 26624
#define ATT_NSTAGE      4
#define ATT_SMEM_BYTES  (ATT_Q_BYTES + ATT_NSTAGE * ATT_STAGE_BYTES)  // 126976
#define ATT_SCALE       0.17677669529663687f

__global__ __launch_bounds__(256) void attn_hmma_kernel(
    const __nv_bfloat16* __restrict__ Qhi, const __nv_bfloat16* __restrict__ Qlo,
    const __nv_bfloat16* __restrict__ Khi, const __nv_bfloat16* __restrict__ Klo,
    const __nv_bfloat16* __restrict__ Vthi, const __nv_bfloat16* __restrict__ Vtlo,
    __nv_bfloat16* __restrict__ AOhi, __nv_bfloat16* __restrict__ AOlo)
{
    extern __shared__ char sm[];
    const uint32_t sb = smem_u32(sm);

    const int tid  = threadIdx.x;
    const int wid  = tid >> 5;
    const int lane = tid & 31;
    const int bh = blockIdx.y;
    const int b = bh >> 4, h = bh & 15;
    const int i0 = blockIdx.x * 128;

    // Load Q tile (hi/lo) once: 128 rows x 64B -> 80B-stride smem
    {
        const char* qh = (const char*)(Qhi + ((size_t)bh * S_LEN + i0) * RANK);
        const char* ql = (const char*)(Qlo + ((size_t)bh * S_LEN + i0) * RANK);
#pragma unroll
        for (int it = 0; it < 2; it++) {
            int idx = tid + it * 256;
            int row = idx >> 2, seg = idx & 3;
            uint32_t so = row * 80 + seg * 16;
            size_t go = (size_t)row * 64 + seg * 16;
            *(uint4*)(sm + so)         = *(const uint4*)(qh + go);
            *(uint4*)(sm + 10240 + so) = *(const uint4*)(ql + go);
        }
    }

    auto issue = [&](int jt, int stg) {
        const uint32_t base = sb + ATT_Q_BYTES + stg * ATT_STAGE_BYTES;
        {
            int row = tid >> 2, seg = tid & 3;
            size_t go = ((size_t)bh * S_LEN + jt * 64 + row) * 64 + seg * 16;
            uint32_t so = row * 80 + seg * 16;
            cp16(base + so,        (const char*)Khi + go);
            cp16(base + 5120 + so, (const char*)Klo + go);
        }
        const size_t vbase = (size_t)bh * HDIM * S_LEN + jt * 64;
        const char* vh = (const char*)(Vthi + vbase);
        const char* vl = (const char*)(Vtlo + vbase);
#pragma unroll
        for (int it = 0; it < 2; it++) {
            int idx = tid + it * 256;
            int d = idx >> 3, seg = idx & 7;
            uint32_t so = d * 128 + ((seg ^ (d & 7)) * 16);
            size_t go = (size_t)d * (S_LEN * 2) + seg * 16;
            cp16(base + 10240 + so, vh + go);
            cp16(base + 18432 + so, vl + go);
        }
    };

    float m0 = -1e30f, m1 = -1e30f, l0 = 0.0f, l1 = 0.0f;
    float o[8][4];
#pragma unroll
    for (int nf = 0; nf < 8; nf++)
#pragma unroll
        for (int k = 0; k < 4; k++) o[nf][k] = 0.0f;

    issue(0, 0); cp_commit();
    issue(1, 1); cp_commit();
    issue(2, 2); cp_commit();

    const int NJT = S_LEN / 64;   // 32
    for (int jt = 0; jt < NJT; jt++) {
        cp_wait<2>();
        __syncthreads();
        if (jt + 3 < NJT) issue(jt + 3, (jt + 3) & 3);
        cp_commit();   // always commit

        const uint32_t base = sb + ATT_Q_BYTES + (jt & 3) * ATT_STAGE_BYTES;

        // ---- S = Q K^T (split, 3-term) ----
        float s[8][4];
#pragma unroll
        for (int nf = 0; nf < 8; nf++)
#pragma unroll
            for (int k = 0; k < 4; k++) s[nf][k] = 0.0f;

#pragma unroll
        for (int ks = 0; ks < 2; ks++) {
            uint32_t lm_off = (lane & 15) * 80 + ks * 32 + (lane >> 4) * 16;
            uint32_t qh[4], ql[4];
            uint32_t qa = sb + (wid * 16) * 80 + lm_off;
            ldm_x4(qh[0], qh[1], qh[2], qh[3], qa);
            ldm_x4(ql[0], ql[1], ql[2], ql[3], qa + 10240);
#pragma unroll
            for (int p = 0; p < 4; p++) {
                uint32_t ka = base + (p * 16) * 80 + lm_off;
                uint32_t h0, h1, h2, h3, o0, o1, o2, o3;
                ldm_x4(h0, h1, h2, h3, ka);
                ldm_x4(o0, o1, o2, o3, ka + 5120);
                mma_bf16(s[2 * p],     qh, h0, h2);
                mma_bf16(s[2 * p],     qh, o0, o2);
                mma_bf16(s[2 * p],     ql, h0, h2);
                mma_bf16(s[2 * p + 1], qh, h1, h3);
                mma_bf16(s[2 * p + 1], qh, o1, o3);
                mma_bf16(s[2 * p + 1], ql, h1, h3);
            }
        }

        // ---- online softmax (fp32) ----
        float mx0 = -1e30f, mx1 = -1e30f;
#pragma unroll
        for (int nf = 0; nf < 8; nf++) {
            mx0 = fmaxf(mx0, fmaxf(s[nf][0], s[nf][1]));
            mx1 = fmaxf(mx1, fmaxf(s[nf][2], s[nf][3]));
        }
#pragma unroll
        for (int off = 1; off <= 2; off <<= 1) {
            mx0 = fmaxf(mx0, __shfl_xor_sync(0xffffffffu, mx0, off));
            mx1 = fmaxf(mx1, __shfl_xor_sync(0xffffffffu, mx1, off));
        }
        mx0 *= ATT_SCALE; mx1 *= ATT_SCALE;
        float nm0 = fmaxf(m0, mx0), nm1 = fmaxf(m1, mx1);
        float al0 = __expf(m0 - nm0), al1 = __expf(m1 - nm1);
        m0 = nm0; m1 = nm1;

        float sum0 = 0.0f, sum1 = 0.0f;
#pragma unroll
        for (int nf = 0; nf < 8; nf++) {
            s[nf][0] = __expf(s[nf][0] * ATT_SCALE - nm0);
            s[nf][1] = __expf(s[nf][1] * ATT_SCALE - nm0);
            s[nf][2] = __expf(s[nf][2] * ATT_SCALE - nm1);
            s[nf][3] = __expf(s[nf][3] * ATT_SCALE - nm1);
            sum0 += s[nf][0] + s[nf][1];
            sum1 += s[nf][2] + s[nf][3];
        }
        l0 = l0 * al0 + sum0;
        l1 = l1 * al1 + sum1;
#pragma unroll
        for (int nf = 0; nf < 8; nf++) {
            o[nf][0] *= al0; o[nf][1] *= al0;
            o[nf][2] *= al1; o[nf][3] *= al1;
        }

        // ---- pack P (hi + residual lo) as A-fragments ----
        uint32_t ph[4][4], pl[4][4];
#pragma unroll
        for (int kf = 0; kf < 4; kf++) {
            split_pack2(s[2 * kf][0],     s[2 * kf][1],     ph[kf][0], pl[kf][0]);
            split_pack2(s[2 * kf][2],     s[2 * kf][3],     ph[kf][1], pl[kf][1]);
            split_pack2(s[2 * kf + 1][0], s[2 * kf + 1][1], ph[kf][2], pl[kf][2]);
            split_pack2(s[2 * kf + 1][2], s[2 * kf + 1][3], ph[kf][3], pl[kf][3]);
        }

        // ---- O += P @ V  (3-term split) ----
#pragma unroll
        for (int kf = 0; kf < 4; kf++) {
#pragma unroll
            for (int pd = 0; pd < 4; pd++) {
                int d = pd * 16 + (lane & 15);
                int seg = kf * 2 + (lane >> 4);
                uint32_t so = d * 128 + ((seg ^ (d & 7)) * 16);
                uint32_t vh0, vh1, vh2, vh3, vl0, vl1, vl2, vl3;
                ldm_x4(vh0, vh1, vh2, vh3, base + 10240 + so);
                ldm_x4(vl0, vl1, vl2, vl3, base + 18432 + so);
                mma_bf16(o[2 * pd],     ph[kf], vh0, vh2);
                mma_bf16(o[2 * pd],     ph[kf], vl0, vl2);
                mma_bf16(o[2 * pd],     pl[kf], vh0, vh2);
                mma_bf16(o[2 * pd + 1], ph[kf], vh1, vh3);
                mma_bf16(o[2 * pd + 1], ph[kf], vl1, vl3);
                mma_bf16(o[2 * pd + 1], pl[kf], vh1, vh3);
            }
        }
    }

    // ---- epilogue: normalize, split, write AO hi/lo ----
#pragma unroll
    for (int off = 1; off <= 2; off <<= 1) {
        l0 += __shfl_xor_sync(0xffffffffu, l0, off);
        l1 += __shfl_xor_sync(0xffffffffu, l1, off);
    }
    float inv0 = 1.0f / l0, inv1 = 1.0f / l1;

    int row0 = b * S_LEN + i0 + wid * 16 + (lane >> 2);
#pragma unroll
    for (int nf = 0; nf < 8; nf++) {
        int col = h * HDIM + nf * 8 + 2 * (lane & 3);
        uint32_t hv, lv;
        split_pack2(o[nf][0] * inv0, o[nf][1] * inv0, hv, lv);
        *(uint32_t*)(AOhi + (size_t)row0 * EMBED + col) = hv;
        *(uint32_t*)(AOlo + (size_t)row0 * EMBED + col) = lv;
        split_pack2(o[nf][2] * inv1, o[nf][3] * inv1, hv, lv);
        *(uint32_t*)(AOhi + (size_t)(row0 + 8) * EMBED + col) = hv;
        *(uint32_t*)(AOlo + (size_t)(row0 + 8) * EMBED + col) = lv;
    }
}

// ---------------------------------------------------------------------------
// Launch
// ---------------------------------------------------------------------------
extern "C" void kernel_launch(void* const* d_in, const int* in_sizes, int n_in,
                              void* d_out, int out_size)
{
    const float* X  = (const float*)d_in[0];
    const float* Wq = (const float*)d_in[1];
    const float* bq = (const float*)d_in[2];
    const float* Wk = (const float*)d_in[3];
    const float* bk = (const float*)d_in[4];
    const float* Wv = (const float*)d_in[5];
    const float* bv = (const float*)d_in[6];
    const float* Wo = (const float*)d_in[7];
    const float* bo = (const float*)d_in[8];
    float* out = (float*)d_out;

    __nv_bfloat16 *Xhi, *Xlo, *AOhi, *AOlo;
    __nv_bfloat16 *Wqh, *Wql, *Wkh, *Wkl, *Wvh, *Wvl, *Woh, *Wol;
    __nv_bfloat16 *Qhi, *Qlo, *Khi, *Klo, *Vth, *Vtl;
    cudaGetSymbolAddress((void**)&Xhi,  g_Xhi);
    cudaGetSymbolAddress((void**)&Xlo,  g_Xlo);
    cudaGetSymbolAddress((void**)&AOhi, g_AOhi);
    cudaGetSymbolAddress((void**)&AOlo, g_AOlo);
    cudaGetSymbolAddress((void**)&Wqh,  g_Wq_hi);
    cudaGetSymbolAddress((void**)&Wql,  g_Wq_lo);
    cudaGetSymbolAddress((void**)&Wkh,  g_Wk_hi);
    cudaGetSymbolAddress((void**)&Wkl,  g_Wk_lo);
    cudaGetSymbolAddress((void**)&Wvh,  g_Wv_hi);
    cudaGetSymbolAddress((void**)&Wvl,  g_Wv_lo);
    cudaGetSymbolAddress((void**)&Woh,  g_Wo_hi);
    cudaGetSymbolAddress((void**)&Wol,  g_Wo_lo);
    cudaGetSymbolAddress((void**)&Qhi,  g_Qhi);
    cudaGetSymbolAddress((void**)&Qlo,  g_Qlo);
    cudaGetSymbolAddress((void**)&Khi,  g_Khi);
    cudaGetSymbolAddress((void**)&Klo,  g_Klo);
    cudaGetSymbolAddress((void**)&Vth,  g_Vthi);
    cudaGetSymbolAddress((void**)&Vtl,  g_Vtlo);

    cudaFuncSetAttribute(hmma_gemm_kernel,
                         cudaFuncAttributeMaxDynamicSharedMemorySize,
                         GEMM_SMEM_BYTES);
    cudaFuncSetAttribute(attn_hmma_kernel,
                         cudaFuncAttributeMaxDynamicSharedMemorySize,
                         ATT_SMEM_BYTES);

    const int nX4 = MROWS * EMBED / 4;

    // 1) input conversions
    split_f32_kernel<<<(nX4 + 255) / 256, 256>>>(X, Xhi, Xlo, nX4);
    transpose_split_kernel<<<dim3(QKCOLS / 32, EMBED / 32), 256>>>(Wq, Wqh, Wql, QKCOLS);
    transpose_split_kernel<<<dim3(QKCOLS / 32, EMBED / 32), 256>>>(Wk, Wkh, Wkl, QKCOLS);
    transpose_split_kernel<<<dim3(EMBED  / 32, EMBED / 32), 256>>>(Wv, Wvh, Wvl, EMBED);
    transpose_split_kernel<<<dim3(EMBED  / 32, EMBED / 32), 256>>>(Wo, Woh, Wol, EMBED);

    // 2) projections with fused split epilogues
    hmma_gemm_kernel<<<dim3(QKCOLS / 128, MROWS / 128), 256, GEMM_SMEM_BYTES>>>(
        Xhi, Xlo, Wqh, Wql, bq, 1, nullptr, Qhi, Qlo, QKCOLS);
    hmma_gemm_kernel<<<dim3(QKCOLS / 128, MROWS / 128), 256, GEMM_SMEM_BYTES>>>(
        Xhi, Xlo, Wkh, Wkl, bk, 1, nullptr, Khi, Klo, QKCOLS);
    hmma_gemm_kernel<<<dim3(EMBED / 128, MROWS / 128), 256, GEMM_SMEM_BYTES>>>(
        Xhi, Xlo, Wvh, Wvl, bv, 2, nullptr, Vth, Vtl, EMBED);

    // 3) attention (HMMA flash, split-precision, writes AO hi/lo)
    attn_hmma_kernel<<<dim3(S_LEN / 128, BH), 256, ATT_SMEM_BYTES>>>(
        Qhi, Qlo, Khi, Klo, Vth, Vtl, AOhi, AOlo);

    // 4) output projection (fp32 out)
    hmma_gemm_kernel<<<dim3(EMBED / 128, MROWS / 128), 256, GEMM_SMEM_BYTES>>>(
        AOhi, AOlo, Woh, Wol, bo, 0, out, nullptr, nullptr, EMBED);
}